// round 11
// baseline (speedup 1.0000x reference)
#include <cuda_runtime.h>
#include <cstdint>

#define D 128
#define BM 64
#define BK 32
#define NTHR 128
#define LDA 36     // smem A leading dim (pad: (36r+c)%32 = (4r+c)%32 -> conflict-free frags)
#define LDH 132    // smem H leading dim (132%32==4, same property)
#define LDB 136    // smem B leading dim ((136k+n)%32 = (8k+n)%32 -> conflict-free frags)

#define MAX_NODES 100000

// scatter-sum scratch (51.2 MB) — __device__ global per allocation rules
__device__ __align__(16) float g_agg[(size_t)MAX_NODES * D];

struct Smem {
    float A[2][BM * LDA];   // 18432 B
    float B[2][BK * LDB];   // 34816 B
    float Hh[BM * LDH];     // 33792 B
    int   sidx[BM];
    int   ridx[BM];
    float bias1[D];
    float bias2[D];
};  // ~88.5 KB -> 2 blocks/SM

__device__ __forceinline__ float to_tf32(float x) {
    uint32_t u;
    asm("cvt.rna.tf32.f32 %0, %1;" : "=r"(u) : "f"(x));
    return __uint_as_float(u);
}

__device__ __forceinline__ void mma_tf32(float d[4], const uint32_t a[4], const uint32_t b[2]) {
    asm volatile(
        "mma.sync.aligned.m16n8k8.row.col.f32.tf32.tf32.f32 "
        "{%0,%1,%2,%3}, {%4,%5,%6,%7}, {%8,%9}, {%0,%1,%2,%3};"
        : "+f"(d[0]), "+f"(d[1]), "+f"(d[2]), "+f"(d[3])
        : "r"(a[0]), "r"(a[1]), "r"(a[2]), "r"(a[3]), "r"(b[0]), "r"(b[1]));
}

// One BK=32 K-chunk of mma for a 64x128 block tile. Warp tile = 32(m) x 64(n).
template <int LDA_T>
__device__ __forceinline__ void mma_chunk(const float* sA, const float* sB,
                                          int warp_m, int warp_n, int lane,
                                          float acc[2][8][4]) {
    const int g = lane >> 2, t = lane & 3;
    #pragma unroll
    for (int ks = 0; ks < 4; ++ks) {
        const int k = ks * 8;
        uint32_t a[2][4];
        #pragma unroll
        for (int mf = 0; mf < 2; ++mf) {
            const int r0 = warp_m * 32 + mf * 16 + g;
            a[mf][0] = __float_as_uint(sA[r0 * LDA_T + k + t]);
            a[mf][1] = __float_as_uint(sA[(r0 + 8) * LDA_T + k + t]);
            a[mf][2] = __float_as_uint(sA[r0 * LDA_T + k + t + 4]);
            a[mf][3] = __float_as_uint(sA[(r0 + 8) * LDA_T + k + t + 4]);
        }
        #pragma unroll
        for (int nf = 0; nf < 8; ++nf) {
            const int col = warp_n * 64 + nf * 8 + g;
            uint32_t b[2];
            b[0] = __float_as_uint(sB[(k + t) * LDB + col]);
            b[1] = __float_as_uint(sB[(k + t + 4) * LDB + col]);
            mma_tf32(acc[0][nf], a[0], b);
            mma_tf32(acc[1][nf], a[1], b);
        }
    }
}

// ---- global -> reg -> (rna tf32) -> smem staging ----

__device__ __forceinline__ void ldg_B(float4 r[8], const float* __restrict__ W, int k0) {
    #pragma unroll
    for (int i = 0; i < 8; ++i) {
        const int idx = threadIdx.x + i * NTHR;       // 0..1023 over 32x32 float4
        const int kr = idx >> 5, c4 = idx & 31;
        r[i] = *reinterpret_cast<const float4*>(W + (size_t)(k0 + kr) * D + c4 * 4);
    }
}

__device__ __forceinline__ void sts_B(float* sB, const float4 r[8]) {
    #pragma unroll
    for (int i = 0; i < 8; ++i) {
        const int idx = threadIdx.x + i * NTHR;
        const int kr = idx >> 5, c4 = idx & 31;
        float4 v = r[i];
        v.x = to_tf32(v.x); v.y = to_tf32(v.y); v.z = to_tf32(v.z); v.w = to_tf32(v.w);
        *reinterpret_cast<float4*>(sB + kr * LDB + c4 * 4) = v;
    }
}

__device__ __forceinline__ void sts_A(float* sA, const float4 r[4]) {
    #pragma unroll
    for (int i = 0; i < 4; ++i) {
        const int idx = threadIdx.x + i * NTHR;       // 0..511 over 64x8 float4
        const int row = idx >> 3, c4 = idx & 7;
        float4 v = r[i];
        v.x = to_tf32(v.x); v.y = to_tf32(v.y); v.z = to_tf32(v.z); v.w = to_tf32(v.w);
        *reinterpret_cast<float4*>(sA + row * LDA + c4 * 4) = v;
    }
}

__device__ __forceinline__ void ldg_A_edge(float4 r[4],
                                           const float* __restrict__ nodes,
                                           const float* __restrict__ edges,
                                           const int* sidx, const int* ridx,
                                           long e0, long E, int chunk) {
    #pragma unroll
    for (int i = 0; i < 4; ++i) {
        const int idx = threadIdx.x + i * NTHR;
        const int row = idx >> 3, c4 = idx & 7;
        const float* src;
        if (chunk < 4)       src = nodes + (size_t)sidx[row] * D + chunk * 32;
        else if (chunk < 8)  src = nodes + (size_t)ridx[row] * D + (chunk - 4) * 32;
        else                 src = edges + (size_t)(e0 + row) * D + (chunk - 8) * 32;
        r[i] = (e0 + row < E) ? *reinterpret_cast<const float4*>(src + c4 * 4)
                              : make_float4(0.f, 0.f, 0.f, 0.f);
    }
}

__device__ __forceinline__ void ldg_A_node(float4 r[4],
                                           const float* __restrict__ nodes,
                                           long n0, long N, int chunk) {
    #pragma unroll
    for (int i = 0; i < 4; ++i) {
        const int idx = threadIdx.x + i * NTHR;
        const int row = idx >> 3, c4 = idx & 7;
        const long n = n0 + row;
        const float* src = (chunk < 4) ? nodes + (size_t)n * D + chunk * 32
                                       : g_agg + (size_t)n * D + (chunk - 4) * 32;
        r[i] = (n < N) ? *reinterpret_cast<const float4*>(src + c4 * 4)
                       : make_float4(0.f, 0.f, 0.f, 0.f);
    }
}

__device__ __forceinline__ void zero_acc(float acc[2][8][4]) {
    #pragma unroll
    for (int mf = 0; mf < 2; ++mf)
        #pragma unroll
        for (int nf = 0; nf < 8; ++nf)
            #pragma unroll
            for (int i = 0; i < 4; ++i) acc[mf][nf][i] = 0.f;
}

// Store acc(+bias1), relu, rna -> Hh; or acc(+bias2) -> Hh (no relu).
__device__ __forceinline__ void acc_to_H(float* Hh, float acc[2][8][4],
                                         const float* bias, int warp_m, int warp_n,
                                         int lane, bool relu_rna) {
    const int g = lane >> 2, t = lane & 3;
    #pragma unroll
    for (int mf = 0; mf < 2; ++mf) {
        const int r0 = warp_m * 32 + mf * 16 + g;
        #pragma unroll
        for (int nf = 0; nf < 8; ++nf) {
            const int col = warp_n * 64 + nf * 8 + 2 * t;
            float2 v0, v1;
            v0.x = acc[mf][nf][0] + bias[col];
            v0.y = acc[mf][nf][1] + bias[col + 1];
            v1.x = acc[mf][nf][2] + bias[col];
            v1.y = acc[mf][nf][3] + bias[col + 1];
            if (relu_rna) {
                v0.x = to_tf32(fmaxf(v0.x, 0.f)); v0.y = to_tf32(fmaxf(v0.y, 0.f));
                v1.x = to_tf32(fmaxf(v1.x, 0.f)); v1.y = to_tf32(fmaxf(v1.y, 0.f));
            }
            *reinterpret_cast<float2*>(&Hh[r0 * LDH + col]) = v0;
            *reinterpret_cast<float2*>(&Hh[(r0 + 8) * LDH + col]) = v1;
        }
    }
}

// =================== edge kernel ===================
__global__ void __launch_bounds__(NTHR, 2)
edge_kernel(const float* __restrict__ nodes, const float* __restrict__ edges,
            const int* __restrict__ senders, const int* __restrict__ receivers,
            const float* __restrict__ We1, const float* __restrict__ be1,
            const float* __restrict__ We2, const float* __restrict__ be2,
            float* __restrict__ out_edges, long E)
{
    extern __shared__ char smem_raw[];
    Smem& S = *reinterpret_cast<Smem*>(smem_raw);
    const long e0 = (long)blockIdx.x * BM;
    const int tid = threadIdx.x, lane = tid & 31;
    const int warp_m = (tid >> 5) & 1, warp_n = tid >> 6;

    if (tid < BM) { const long e = e0 + tid; S.sidx[tid] = (e < E) ? senders[e] : 0; }
    else          { const int r = tid - BM; const long e = e0 + r; S.ridx[r] = (e < E) ? receivers[e] : 0; }
    S.bias1[tid] = be1[tid];
    S.bias2[tid] = be2[tid];
    __syncthreads();

    float acc[2][8][4];
    zero_acc(acc);

    float4 ra[4], rb[8];

    // ---- GEMM1: [64,384] x [384,128], 12 K-chunks, double buffered ----
    ldg_A_edge(ra, nodes, edges, S.sidx, S.ridx, e0, E, 0);
    ldg_B(rb, We1, 0);
    sts_A(S.A[0], ra); sts_B(S.B[0], rb);
    __syncthreads();
    #pragma unroll 1
    for (int c = 0; c < 12; ++c) {
        const int cur = c & 1;
        if (c + 1 < 12) {
            ldg_A_edge(ra, nodes, edges, S.sidx, S.ridx, e0, E, c + 1);
            ldg_B(rb, We1, (c + 1) * BK);
        }
        mma_chunk<LDA>(S.A[cur], S.B[cur], warp_m, warp_n, lane, acc);
        if (c + 1 < 12) { sts_A(S.A[cur ^ 1], ra); sts_B(S.B[cur ^ 1], rb); }
        __syncthreads();
    }

    // h = rna(relu(acc + b1)) -> Hh ; prefetch W2 chunk0
    ldg_B(rb, We2, 0);
    acc_to_H(S.Hh, acc, S.bias1, warp_m, warp_n, lane, true);
    zero_acc(acc);
    sts_B(S.B[0], rb);
    __syncthreads();

    // ---- GEMM2: [64,128] x [128,128], 4 K-chunks ----
    #pragma unroll 1
    for (int c = 0; c < 4; ++c) {
        const int cur = c & 1;
        if (c + 1 < 4) ldg_B(rb, We2, (c + 1) * BK);
        mma_chunk<LDH>(S.Hh + c * BK, S.B[cur], warp_m, warp_n, lane, acc);
        if (c + 1 < 4) sts_B(S.B[cur ^ 1], rb);
        __syncthreads();
    }

    // y = acc + b2 -> Hh
    acc_to_H(S.Hh, acc, S.bias2, warp_m, warp_n, lane, false);
    __syncthreads();

    // new_edges = edges + y ; agg[recv] += y (vectorized red)
    #pragma unroll 1
    for (int i = 0; i < 16; ++i) {
        const int idx = tid + i * NTHR;            // 0..2047 over 64x32 float4
        const int row = idx >> 5, c4 = idx & 31;
        const long e = e0 + row;
        if (e < E) {
            const float4 ef = *reinterpret_cast<const float4*>(edges + (size_t)e * D + c4 * 4);
            const float4 y  = *reinterpret_cast<const float4*>(&S.Hh[row * LDH + c4 * 4]);
            float4 o;
            o.x = ef.x + y.x; o.y = ef.y + y.y; o.z = ef.z + y.z; o.w = ef.w + y.w;
            *reinterpret_cast<float4*>(out_edges + (size_t)e * D + c4 * 4) = o;
            float* dst = g_agg + (size_t)S.ridx[row] * D + c4 * 4;
            asm volatile("red.global.add.v4.f32 [%0], {%1,%2,%3,%4};"
                         :: "l"(dst), "f"(y.x), "f"(y.y), "f"(y.z), "f"(y.w) : "memory");
        }
    }
}

// =================== node kernel ===================
__global__ void __launch_bounds__(NTHR, 2)
node_kernel(const float* __restrict__ nodes,
            const float* __restrict__ Wn1, const float* __restrict__ bn1,
            const float* __restrict__ Wn2, const float* __restrict__ bn2,
            float* __restrict__ out_nodes, long N)
{
    extern __shared__ char smem_raw[];
    Smem& S = *reinterpret_cast<Smem*>(smem_raw);
    const long n0 = (long)blockIdx.x * BM;
    const int tid = threadIdx.x, lane = tid & 31;
    const int warp_m = (tid >> 5) & 1, warp_n = tid >> 6;

    S.bias1[tid] = bn1[tid];
    S.bias2[tid] = bn2[tid];
    __syncthreads();

    float acc[2][8][4];
    zero_acc(acc);

    float4 ra[4], rb[8];

    // ---- GEMM1: [64,256] x [256,128], 8 K-chunks ----
    ldg_A_node(ra, nodes, n0, N, 0);
    ldg_B(rb, Wn1, 0);
    sts_A(S.A[0], ra); sts_B(S.B[0], rb);
    __syncthreads();
    #pragma unroll 1
    for (int c = 0; c < 8; ++c) {
        const int cur = c & 1;
        if (c + 1 < 8) {
            ldg_A_node(ra, nodes, n0, N, c + 1);
            ldg_B(rb, Wn1, (c + 1) * BK);
        }
        mma_chunk<LDA>(S.A[cur], S.B[cur], warp_m, warp_n, lane, acc);
        if (c + 1 < 8) { sts_A(S.A[cur ^ 1], ra); sts_B(S.B[cur ^ 1], rb); }
        __syncthreads();
    }

    ldg_B(rb, Wn2, 0);
    acc_to_H(S.Hh, acc, S.bias1, warp_m, warp_n, lane, true);
    zero_acc(acc);
    sts_B(S.B[0], rb);
    __syncthreads();

    // ---- GEMM2: [64,128] x [128,128] ----
    #pragma unroll 1
    for (int c = 0; c < 4; ++c) {
        const int cur = c & 1;
        if (c + 1 < 4) ldg_B(rb, Wn2, (c + 1) * BK);
        mma_chunk<LDH>(S.Hh + c * BK, S.B[cur], warp_m, warp_n, lane, acc);
        if (c + 1 < 4) sts_B(S.B[cur ^ 1], rb);
        __syncthreads();
    }

    acc_to_H(S.Hh, acc, S.bias2, warp_m, warp_n, lane, false);
    __syncthreads();

    // new_nodes = nodes + y
    #pragma unroll 1
    for (int i = 0; i < 16; ++i) {
        const int idx = tid + i * NTHR;
        const int row = idx >> 5, c4 = idx & 31;
        const long n = n0 + row;
        if (n < N) {
            const float4 nf = *reinterpret_cast<const float4*>(nodes + (size_t)n * D + c4 * 4);
            const float4 y  = *reinterpret_cast<const float4*>(&S.Hh[row * LDH + c4 * 4]);
            float4 o;
            o.x = nf.x + y.x; o.y = nf.y + y.y; o.z = nf.z + y.z; o.w = nf.w + y.w;
            *reinterpret_cast<float4*>(out_nodes + (size_t)n * D + c4 * 4) = o;
        }
    }
}

// =================== zero the scatter scratch ===================
__global__ void zero_agg_kernel(long n4) {
    float4* p = reinterpret_cast<float4*>(g_agg);
    long i = (long)blockIdx.x * blockDim.x + threadIdx.x;
    const long stride = (long)gridDim.x * blockDim.x;
    const float4 z = make_float4(0.f, 0.f, 0.f, 0.f);
    for (; i < n4; i += stride) p[i] = z;
}

extern "C" void kernel_launch(void* const* d_in, const int* in_sizes, int n_in,
                              void* d_out, int out_size) {
    const float* nodes     = (const float*)d_in[0];
    const float* edges     = (const float*)d_in[1];
    const int*   senders   = (const int*)d_in[2];
    const int*   receivers = (const int*)d_in[3];
    const float* We1 = (const float*)d_in[4];
    const float* be1 = (const float*)d_in[5];
    const float* We2 = (const float*)d_in[6];
    const float* be2 = (const float*)d_in[7];
    const float* Wn1 = (const float*)d_in[8];
    const float* bn1 = (const float*)d_in[9];
    const float* Wn2 = (const float*)d_in[10];
    const float* bn2 = (const float*)d_in[11];

    const long N = (long)in_sizes[0] / D;
    const long E = (long)in_sizes[2];

    float* out_nodes = (float*)d_out;               // [N, D] first
    float* out_edges = out_nodes + (size_t)N * D;   // then [E, D]

    const int smem = (int)sizeof(Smem);
    cudaFuncSetAttribute(edge_kernel, cudaFuncAttributeMaxDynamicSharedMemorySize, smem);
    cudaFuncSetAttribute(node_kernel, cudaFuncAttributeMaxDynamicSharedMemorySize, smem);

    zero_agg_kernel<<<2048, 256>>>(N * D / 4);
    edge_kernel<<<(int)((E + BM - 1) / BM), NTHR, smem>>>(
        nodes, edges, senders, receivers, We1, be1, We2, be2, out_edges, E);
    node_kernel<<<(int)((N + BM - 1) / BM), NTHR, smem>>>(
        nodes, Wn1, bn1, Wn2, bn2, out_nodes, N);
}

// round 12
// speedup vs baseline: 1.0009x; 1.0009x over previous
#include <cuda_runtime.h>
#include <cstdint>

#define D 128
#define BM 64
#define BK 32
#define NTHR 128
#define LDA 36     // smem A leading dim (pad: (36r+c)%32 = (4r+c)%32 -> conflict-free frags)
#define LDH 132    // smem H leading dim (132%32==4, same property)
#define LDB 136    // smem B leading dim ((136k+n)%32 = (8k+n)%32 -> conflict-free frags)

#define MAX_NODES 100000

// scatter-sum scratch (51.2 MB) — __device__ global per allocation rules
__device__ __align__(16) float g_agg[(size_t)MAX_NODES * D];

struct Smem {
    float A[2][BM * LDA];   // 18432 B
    float B[2][BK * LDB];   // 34816 B
    float Hh[BM * LDH];     // 33792 B
    int   sidx[BM];
    int   ridx[BM];
    float bias1[D];
    float bias2[D];
};  // ~88.5 KB -> 2 blocks/SM

__device__ __forceinline__ float to_tf32(float x) {
    uint32_t u;
    asm("cvt.rna.tf32.f32 %0, %1;" : "=r"(u) : "f"(x));
    return __uint_as_float(u);
}

__device__ __forceinline__ void mma_tf32(float d[4], const uint32_t a[4], const uint32_t b[2]) {
    asm volatile(
        "mma.sync.aligned.m16n8k8.row.col.f32.tf32.tf32.f32 "
        "{%0,%1,%2,%3}, {%4,%5,%6,%7}, {%8,%9}, {%0,%1,%2,%3};"
        : "+f"(d[0]), "+f"(d[1]), "+f"(d[2]), "+f"(d[3])
        : "r"(a[0]), "r"(a[1]), "r"(a[2]), "r"(a[3]), "r"(b[0]), "r"(b[1]));
}

// One BK=32 K-chunk of mma for a 64x128 block tile. Warp tile = 32(m) x 64(n).
template <int LDA_T>
__device__ __forceinline__ void mma_chunk(const float* sA, const float* sB,
                                          int warp_m, int warp_n, int lane,
                                          float acc[2][8][4]) {
    const int g = lane >> 2, t = lane & 3;
    #pragma unroll
    for (int ks = 0; ks < 4; ++ks) {
        const int k = ks * 8;
        uint32_t a[2][4];
        #pragma unroll
        for (int mf = 0; mf < 2; ++mf) {
            const int r0 = warp_m * 32 + mf * 16 + g;
            a[mf][0] = __float_as_uint(sA[r0 * LDA_T + k + t]);
            a[mf][1] = __float_as_uint(sA[(r0 + 8) * LDA_T + k + t]);
            a[mf][2] = __float_as_uint(sA[r0 * LDA_T + k + t + 4]);
            a[mf][3] = __float_as_uint(sA[(r0 + 8) * LDA_T + k + t + 4]);
        }
        #pragma unroll
        for (int nf = 0; nf < 8; ++nf) {
            const int col = warp_n * 64 + nf * 8 + g;
            uint32_t b[2];
            b[0] = __float_as_uint(sB[(k + t) * LDB + col]);
            b[1] = __float_as_uint(sB[(k + t + 4) * LDB + col]);
            mma_tf32(acc[0][nf], a[0], b);
            mma_tf32(acc[1][nf], a[1], b);
        }
    }
}

// ---- global -> reg -> (rna tf32) -> smem staging ----

__device__ __forceinline__ void ldg_B(float4 r[8], const float* __restrict__ W, int k0) {
    #pragma unroll
    for (int i = 0; i < 8; ++i) {
        const int idx = threadIdx.x + i * NTHR;       // 0..1023 over 32x32 float4
        const int kr = idx >> 5, c4 = idx & 31;
        r[i] = *reinterpret_cast<const float4*>(W + (size_t)(k0 + kr) * D + c4 * 4);
    }
}

__device__ __forceinline__ void sts_B(float* sB, const float4 r[8]) {
    #pragma unroll
    for (int i = 0; i < 8; ++i) {
        const int idx = threadIdx.x + i * NTHR;
        const int kr = idx >> 5, c4 = idx & 31;
        float4 v = r[i];
        v.x = to_tf32(v.x); v.y = to_tf32(v.y); v.z = to_tf32(v.z); v.w = to_tf32(v.w);
        *reinterpret_cast<float4*>(sB + kr * LDB + c4 * 4) = v;
    }
}

__device__ __forceinline__ void sts_A(float* sA, const float4 r[4]) {
    #pragma unroll
    for (int i = 0; i < 4; ++i) {
        const int idx = threadIdx.x + i * NTHR;       // 0..511 over 64x8 float4
        const int row = idx >> 3, c4 = idx & 7;
        float4 v = r[i];
        v.x = to_tf32(v.x); v.y = to_tf32(v.y); v.z = to_tf32(v.z); v.w = to_tf32(v.w);
        *reinterpret_cast<float4*>(sA + row * LDA + c4 * 4) = v;
    }
}

__device__ __forceinline__ void ldg_A_edge(float4 r[4],
                                           const float* __restrict__ nodes,
                                           const float* __restrict__ edges,
                                           const int* sidx, const int* ridx,
                                           long e0, long E, int chunk) {
    #pragma unroll
    for (int i = 0; i < 4; ++i) {
        const int idx = threadIdx.x + i * NTHR;
        const int row = idx >> 3, c4 = idx & 7;
        const float* src;
        if (chunk < 4)       src = nodes + (size_t)sidx[row] * D + chunk * 32;
        else if (chunk < 8)  src = nodes + (size_t)ridx[row] * D + (chunk - 4) * 32;
        else                 src = edges + (size_t)(e0 + row) * D + (chunk - 8) * 32;
        r[i] = (e0 + row < E) ? *reinterpret_cast<const float4*>(src + c4 * 4)
                              : make_float4(0.f, 0.f, 0.f, 0.f);
    }
}

__device__ __forceinline__ void ldg_A_node(float4 r[4],
                                           const float* __restrict__ nodes,
                                           long n0, long N, int chunk) {
    #pragma unroll
    for (int i = 0; i < 4; ++i) {
        const int idx = threadIdx.x + i * NTHR;
        const int row = idx >> 3, c4 = idx & 7;
        const long n = n0 + row;
        const float* src = (chunk < 4) ? nodes + (size_t)n * D + chunk * 32
                                       : g_agg + (size_t)n * D + (chunk - 4) * 32;
        r[i] = (n < N) ? *reinterpret_cast<const float4*>(src + c4 * 4)
                       : make_float4(0.f, 0.f, 0.f, 0.f);
    }
}

__device__ __forceinline__ void zero_acc(float acc[2][8][4]) {
    #pragma unroll
    for (int mf = 0; mf < 2; ++mf)
        #pragma unroll
        for (int nf = 0; nf < 8; ++nf)
            #pragma unroll
            for (int i = 0; i < 4; ++i) acc[mf][nf][i] = 0.f;
}

// Store acc(+bias1), relu, rna -> Hh; or acc(+bias2) -> Hh (no relu).
__device__ __forceinline__ void acc_to_H(float* Hh, float acc[2][8][4],
                                         const float* bias, int warp_m, int warp_n,
                                         int lane, bool relu_rna) {
    const int g = lane >> 2, t = lane & 3;
    #pragma unroll
    for (int mf = 0; mf < 2; ++mf) {
        const int r0 = warp_m * 32 + mf * 16 + g;
        #pragma unroll
        for (int nf = 0; nf < 8; ++nf) {
            const int col = warp_n * 64 + nf * 8 + 2 * t;
            float2 v0, v1;
            v0.x = acc[mf][nf][0] + bias[col];
            v0.y = acc[mf][nf][1] + bias[col + 1];
            v1.x = acc[mf][nf][2] + bias[col];
            v1.y = acc[mf][nf][3] + bias[col + 1];
            if (relu_rna) {
                v0.x = to_tf32(fmaxf(v0.x, 0.f)); v0.y = to_tf32(fmaxf(v0.y, 0.f));
                v1.x = to_tf32(fmaxf(v1.x, 0.f)); v1.y = to_tf32(fmaxf(v1.y, 0.f));
            }
            *reinterpret_cast<float2*>(&Hh[r0 * LDH + col]) = v0;
            *reinterpret_cast<float2*>(&Hh[(r0 + 8) * LDH + col]) = v1;
        }
    }
}

// =================== edge kernel ===================
__global__ void __launch_bounds__(NTHR, 2)
edge_kernel(const float* __restrict__ nodes, const float* __restrict__ edges,
            const int* __restrict__ senders, const int* __restrict__ receivers,
            const float* __restrict__ We1, const float* __restrict__ be1,
            const float* __restrict__ We2, const float* __restrict__ be2,
            float* __restrict__ out_edges, long E)
{
    extern __shared__ char smem_raw[];
    Smem& S = *reinterpret_cast<Smem*>(smem_raw);
    const long e0 = (long)blockIdx.x * BM;
    const int tid = threadIdx.x, lane = tid & 31;
    const int warp_m = (tid >> 5) & 1, warp_n = tid >> 6;

    if (tid < BM) { const long e = e0 + tid; S.sidx[tid] = (e < E) ? senders[e] : 0; }
    else          { const int r = tid - BM; const long e = e0 + r; S.ridx[r] = (e < E) ? receivers[e] : 0; }
    S.bias1[tid] = be1[tid];
    S.bias2[tid] = be2[tid];
    __syncthreads();

    float acc[2][8][4];
    zero_acc(acc);

    float4 ra[4], rb[8];

    // ---- GEMM1: [64,384] x [384,128], 12 K-chunks, double buffered ----
    ldg_A_edge(ra, nodes, edges, S.sidx, S.ridx, e0, E, 0);
    ldg_B(rb, We1, 0);
    sts_A(S.A[0], ra); sts_B(S.B[0], rb);
    __syncthreads();
    #pragma unroll 1
    for (int c = 0; c < 12; ++c) {
        const int cur = c & 1;
        if (c + 1 < 12) {
            ldg_A_edge(ra, nodes, edges, S.sidx, S.ridx, e0, E, c + 1);
            ldg_B(rb, We1, (c + 1) * BK);
        }
        mma_chunk<LDA>(S.A[cur], S.B[cur], warp_m, warp_n, lane, acc);
        if (c + 1 < 12) { sts_A(S.A[cur ^ 1], ra); sts_B(S.B[cur ^ 1], rb); }
        __syncthreads();
    }

    // h = rna(relu(acc + b1)) -> Hh ; prefetch W2 chunk0
    ldg_B(rb, We2, 0);
    acc_to_H(S.Hh, acc, S.bias1, warp_m, warp_n, lane, true);
    zero_acc(acc);
    sts_B(S.B[0], rb);
    __syncthreads();

    // ---- GEMM2: [64,128] x [128,128], 4 K-chunks ----
    #pragma unroll 1
    for (int c = 0; c < 4; ++c) {
        const int cur = c & 1;
        if (c + 1 < 4) ldg_B(rb, We2, (c + 1) * BK);
        mma_chunk<LDH>(S.Hh + c * BK, S.B[cur], warp_m, warp_n, lane, acc);
        if (c + 1 < 4) sts_B(S.B[cur ^ 1], rb);
        __syncthreads();
    }

    // y = acc + b2 -> Hh
    acc_to_H(S.Hh, acc, S.bias2, warp_m, warp_n, lane, false);
    __syncthreads();

    // new_edges = edges + y ; agg[recv] += y (vectorized red)
    #pragma unroll 1
    for (int i = 0; i < 16; ++i) {
        const int idx = tid + i * NTHR;            // 0..2047 over 64x32 float4
        const int row = idx >> 5, c4 = idx & 31;
        const long e = e0 + row;
        if (e < E) {
            const float4 ef = *reinterpret_cast<const float4*>(edges + (size_t)e * D + c4 * 4);
            const float4 y  = *reinterpret_cast<const float4*>(&S.Hh[row * LDH + c4 * 4]);
            float4 o;
            o.x = ef.x + y.x; o.y = ef.y + y.y; o.z = ef.z + y.z; o.w = ef.w + y.w;
            *reinterpret_cast<float4*>(out_edges + (size_t)e * D + c4 * 4) = o;
            float* dst = g_agg + (size_t)S.ridx[row] * D + c4 * 4;
            asm volatile("red.global.add.v4.f32 [%0], {%1,%2,%3,%4};"
                         :: "l"(dst), "f"(y.x), "f"(y.y), "f"(y.z), "f"(y.w) : "memory");
        }
    }
}

// =================== node kernel ===================
__global__ void __launch_bounds__(NTHR, 2)
node_kernel(const float* __restrict__ nodes,
            const float* __restrict__ Wn1, const float* __restrict__ bn1,
            const float* __restrict__ Wn2, const float* __restrict__ bn2,
            float* __restrict__ out_nodes, long N)
{
    extern __shared__ char smem_raw[];
    Smem& S = *reinterpret_cast<Smem*>(smem_raw);
    const long n0 = (long)blockIdx.x * BM;
    const int tid = threadIdx.x, lane = tid & 31;
    const int warp_m = (tid >> 5) & 1, warp_n = tid >> 6;

    S.bias1[tid] = bn1[tid];
    S.bias2[tid] = bn2[tid];
    __syncthreads();

    float acc[2][8][4];
    zero_acc(acc);

    float4 ra[4], rb[8];

    // ---- GEMM1: [64,256] x [256,128], 8 K-chunks ----
    ldg_A_node(ra, nodes, n0, N, 0);
    ldg_B(rb, Wn1, 0);
    sts_A(S.A[0], ra); sts_B(S.B[0], rb);
    __syncthreads();
    #pragma unroll 1
    for (int c = 0; c < 8; ++c) {
        const int cur = c & 1;
        if (c + 1 < 8) {
            ldg_A_node(ra, nodes, n0, N, c + 1);
            ldg_B(rb, Wn1, (c + 1) * BK);
        }
        mma_chunk<LDA>(S.A[cur], S.B[cur], warp_m, warp_n, lane, acc);
        if (c + 1 < 8) { sts_A(S.A[cur ^ 1], ra); sts_B(S.B[cur ^ 1], rb); }
        __syncthreads();
    }

    ldg_B(rb, Wn2, 0);
    acc_to_H(S.Hh, acc, S.bias1, warp_m, warp_n, lane, true);
    zero_acc(acc);
    sts_B(S.B[0], rb);
    __syncthreads();

    // ---- GEMM2: [64,128] x [128,128] ----
    #pragma unroll 1
    for (int c = 0; c < 4; ++c) {
        const int cur = c & 1;
        if (c + 1 < 4) ldg_B(rb, Wn2, (c + 1) * BK);
        mma_chunk<LDH>(S.Hh + c * BK, S.B[cur], warp_m, warp_n, lane, acc);
        if (c + 1 < 4) sts_B(S.B[cur ^ 1], rb);
        __syncthreads();
    }

    acc_to_H(S.Hh, acc, S.bias2, warp_m, warp_n, lane, false);
    __syncthreads();

    // new_nodes = nodes + y
    #pragma unroll 1
    for (int i = 0; i < 16; ++i) {
        const int idx = tid + i * NTHR;
        const int row = idx >> 5, c4 = idx & 31;
        const long n = n0 + row;
        if (n < N) {
            const float4 nf = *reinterpret_cast<const float4*>(nodes + (size_t)n * D + c4 * 4);
            const float4 y  = *reinterpret_cast<const float4*>(&S.Hh[row * LDH + c4 * 4]);
            float4 o;
            o.x = nf.x + y.x; o.y = nf.y + y.y; o.z = nf.z + y.z; o.w = nf.w + y.w;
            *reinterpret_cast<float4*>(out_nodes + (size_t)n * D + c4 * 4) = o;
        }
    }
}

// =================== zero the scatter scratch ===================
__global__ void zero_agg_kernel(long n4) {
    float4* p = reinterpret_cast<float4*>(g_agg);
    long i = (long)blockIdx.x * blockDim.x + threadIdx.x;
    const long stride = (long)gridDim.x * blockDim.x;
    const float4 z = make_float4(0.f, 0.f, 0.f, 0.f);
    for (; i < n4; i += stride) p[i] = z;
}

extern "C" void kernel_launch(void* const* d_in, const int* in_sizes, int n_in,
                              void* d_out, int out_size) {
    const float* nodes     = (const float*)d_in[0];
    const float* edges     = (const float*)d_in[1];
    const int*   senders   = (const int*)d_in[2];
    const int*   receivers = (const int*)d_in[3];
    const float* We1 = (const float*)d_in[4];
    const float* be1 = (const float*)d_in[5];
    const float* We2 = (const float*)d_in[6];
    const float* be2 = (const float*)d_in[7];
    const float* Wn1 = (const float*)d_in[8];
    const float* bn1 = (const float*)d_in[9];
    const float* Wn2 = (const float*)d_in[10];
    const float* bn2 = (const float*)d_in[11];

    const long N = (long)in_sizes[0] / D;
    const long E = (long)in_sizes[2];

    float* out_nodes = (float*)d_out;               // [N, D] first
    float* out_edges = out_nodes + (size_t)N * D;   // then [E, D]

    const int smem = (int)sizeof(Smem);
    cudaFuncSetAttribute(edge_kernel, cudaFuncAttributeMaxDynamicSharedMemorySize, smem);
    cudaFuncSetAttribute(node_kernel, cudaFuncAttributeMaxDynamicSharedMemorySize, smem);

    zero_agg_kernel<<<2048, 256>>>(N * D / 4);
    edge_kernel<<<(int)((E + BM - 1) / BM), NTHR, smem>>>(
        nodes, edges, senders, receivers, We1, be1, We2, be2, out_edges, E);
    node_kernel<<<(int)((N + BM - 1) / BM), NTHR, smem>>>(
        nodes, Wn1, bn1, Wn2, bn2, out_nodes, N);
}